// round 13
// baseline (speedup 1.0000x reference)
#include <cuda_runtime.h>

// SharedSharedLoss: mean off-diagonal pairwise squared L2 distance / C.
// Identity: sum_{i,j} ||a_i - a_j||^2 = 2N * S2 - 2 * ||colsum||^2
//   S2 = sum of squares of all elements, colsum = per-column sums.
// Single fused kernel: 16 column-strips x 8 row-chunks = 128 blocks x 256 thr.
// Each block reduces its strip to 32 column partials + 1 s2 partial (16 KB
// total cross-block state); the last block to finish does the tiny final
// reduce (threadfence pattern). Deterministic: no float atomics; completion
// counter self-resets so graph replays are identical.
//
// FINAL (converged, R3-R12): measured 8.19 / 8.22 / 8.29 / 8.42 us across
// four runs of this exact source — the harness noise band. The bench sits
// at a ~8.2 us per-replay floor (graph replay + ramp-clock serial latency;
// the 8 MB input is L2-resident across replays). All structural alternatives
// (split launches, PDL overlap, column-complete decomposition, other
// grid/block shapes, thinner tails) measured equal or worse.

#define N_ROWS 4096
#define N_COLS 512
#define N_COLS4 128                  // float4 groups per row
#define N_STRIPS 16                  // column strips of 32 cols (8 float4 groups)
#define N_CHUNKS 8                   // row chunks of 512 rows
#define GRID (N_STRIPS * N_CHUNKS)   // 128 blocks
#define BLK 256                      // 8 groups x 32 row-lanes
#define ROWS_PER_CHUNK (N_ROWS / N_CHUNKS)        // 512
#define ROWS_PER_THREAD (ROWS_PER_CHUNK / 32)     // 16 (fully unrolled MLP)

// Deterministic scratch (no float atomics anywhere).
__device__ float g_colpart[GRID * 32];   // [rc*16+cs][32 cols] = 16 KB
__device__ float g_s2part[GRID];
__device__ unsigned int g_count = 0;     // completion counter (reset by last block)

__global__ __launch_bounds__(BLK) void fused_kernel(const float* __restrict__ A,
                                                    float* __restrict__ out) {
    const int t  = threadIdx.x;
    const int g  = t & 7;            // float4 group within strip (0..7)
    const int r0 = t >> 3;           // row lane (0..31)
    const int b  = blockIdx.x;
    const int cs = b & (N_STRIPS - 1);   // column strip
    const int rc = b >> 4;               // row chunk

    const float4* __restrict__ A4 = reinterpret_cast<const float4*>(A);

    // ---- Streaming phase: 512 rows x 32 cols per block ----
    float4 c = make_float4(0.f, 0.f, 0.f, 0.f);
    float s2 = 0.f;

    const int base = (rc * ROWS_PER_CHUNK + r0) * N_COLS4 + cs * 8 + g;
    #pragma unroll
    for (int i = 0; i < ROWS_PER_THREAD; i++) {
        float4 v = A4[base + i * 32 * N_COLS4];
        c.x += v.x; c.y += v.y; c.z += v.z; c.w += v.w;
        s2 += v.x * v.x + v.y * v.y + v.z * v.z + v.w * v.w;
    }

    // ---- Block reduce: colsums over the 32 row-lanes ----
    __shared__ float4 sh[BLK];
    __shared__ float warp_s2[BLK / 32];
    sh[t] = c;

    #pragma unroll
    for (int off = 16; off > 0; off >>= 1)
        s2 += __shfl_down_sync(0xFFFFFFFFu, s2, off);
    if ((t & 31) == 0) warp_s2[t >> 5] = s2;
    __syncthreads();

    // Tree-reduce sh over the r0 dimension (index = g + 8*r0).
    #pragma unroll
    for (int off = 128; off >= 8; off >>= 1) {
        if (t < off) {
            float4 o = sh[t + off];
            float4 m = sh[t];
            sh[t] = make_float4(m.x + o.x, m.y + o.y, m.z + o.z, m.w + o.w);
        }
        __syncthreads();
    }

    if (t < 8)
        reinterpret_cast<float4*>(g_colpart)[b * 8 + t] = sh[t];
    if (t == 0) {
        float tot = 0.f;
        #pragma unroll
        for (int w = 0; w < BLK / 32; w++) tot += warp_s2[w];
        g_s2part[b] = tot;
    }

    // ---- Last-block-done final reduce ----
    __threadfence();
    __syncthreads();
    __shared__ bool isLast;
    if (t == 0) {
        unsigned int old = atomicAdd(&g_count, 1u);
        isLast = (old == GRID - 1);
    }
    __syncthreads();
    if (!isLast) return;

    // Column sums: thread t handles cols t and t+256.
    // g_colpart layout: [(rc*16+cs)*32 + localcol]; col = cs*32+lc -> float index
    // rc*512 + col. Coalesced across threads.
    double dnrm = 0.0;
    #pragma unroll
    for (int k = 0; k < 2; k++) {
        const int col = t + k * 256;
        float s = 0.f;
        #pragma unroll
        for (int r = 0; r < N_CHUNKS; r++)
            s += g_colpart[r * N_COLS + col];
        dnrm += (double)s * (double)s;
    }
    double ds2 = (t < GRID) ? (double)g_s2part[t] : 0.0;

    // Reduce 256 doubles (8 warps) via shuffles + shared.
    __shared__ double w_nrm[BLK / 32];
    __shared__ double w_s2d[BLK / 32];
    #pragma unroll
    for (int off = 16; off > 0; off >>= 1) {
        dnrm += __shfl_down_sync(0xFFFFFFFFu, dnrm, off);
        ds2  += __shfl_down_sync(0xFFFFFFFFu, ds2, off);
    }
    if ((t & 31) == 0) { w_nrm[t >> 5] = dnrm; w_s2d[t >> 5] = ds2; }
    __syncthreads();

    if (t == 0) {
        double NS = 0.0, S2 = 0.0;
        #pragma unroll
        for (int w = 0; w < BLK / 32; w++) { NS += w_nrm[w]; S2 += w_s2d[w]; }
        const double N = (double)N_ROWS;
        const double C = (double)N_COLS;
        double total = (2.0 * N * S2 - 2.0 * NS) / C;
        out[0] = (float)(total / (N * (N - 1.0)));
        g_count = 0;   // reset for next graph replay
    }
}

extern "C" void kernel_launch(void* const* d_in, const int* in_sizes, int n_in,
                              void* d_out, int out_size) {
    const float* A = (const float*)d_in[0];
    float* out = (float*)d_out;
    (void)in_sizes; (void)n_in; (void)out_size;

    fused_kernel<<<GRID, BLK>>>(A, out);
}

// round 14
// speedup vs baseline: 1.0695x; 1.0695x over previous
#include <cuda_runtime.h>

// SharedSharedLoss: mean off-diagonal pairwise squared L2 distance / C.
// Identity: sum_{i,j} ||a_i - a_j||^2 = 2N * S2 - 2 * ||colsum||^2
//   S2 = sum of squares of all elements, colsum = per-column sums.
// Single fused kernel: 16 column-strips x 8 row-chunks = 128 blocks x 256 thr.
// Each block reduces its strip to 32 column partials + 1 s2 partial (16 KB
// total cross-block state); the last block to finish does the tiny final
// reduce (threadfence pattern). Deterministic: no float atomics; completion
// counter self-resets so graph replays are identical.
//
// FINAL (converged, R3-R13): this exact source measured
// 8.19 / 8.22 / 8.29 / 8.42 / 8.86 us across five runs — that spread IS the
// harness noise band. The bench sits at a ~8.2 us per-replay floor (graph
// replay + ramp-clock serial latency; the mandatory 8 MB read is already at
// burst rate). All structural alternatives tested (split launches, PDL
// overlap, column-complete decomposition, 64/256-block grids, 512-thread
// blocks, thinner tails) measured equal or worse. Session win: analytic
// O(N*C) reformulation of the O(N^2) reference, 18.8 -> 8.2 us.

#define N_ROWS 4096
#define N_COLS 512
#define N_COLS4 128                  // float4 groups per row
#define N_STRIPS 16                  // column strips of 32 cols (8 float4 groups)
#define N_CHUNKS 8                   // row chunks of 512 rows
#define GRID (N_STRIPS * N_CHUNKS)   // 128 blocks
#define BLK 256                      // 8 groups x 32 row-lanes
#define ROWS_PER_CHUNK (N_ROWS / N_CHUNKS)        // 512
#define ROWS_PER_THREAD (ROWS_PER_CHUNK / 32)     // 16 (fully unrolled MLP)

// Deterministic scratch (no float atomics anywhere).
__device__ float g_colpart[GRID * 32];   // [rc*16+cs][32 cols] = 16 KB
__device__ float g_s2part[GRID];
__device__ unsigned int g_count = 0;     // completion counter (reset by last block)

__global__ __launch_bounds__(BLK) void fused_kernel(const float* __restrict__ A,
                                                    float* __restrict__ out) {
    const int t  = threadIdx.x;
    const int g  = t & 7;            // float4 group within strip (0..7)
    const int r0 = t >> 3;           // row lane (0..31)
    const int b  = blockIdx.x;
    const int cs = b & (N_STRIPS - 1);   // column strip
    const int rc = b >> 4;               // row chunk

    const float4* __restrict__ A4 = reinterpret_cast<const float4*>(A);

    // ---- Streaming phase: 512 rows x 32 cols per block ----
    float4 c = make_float4(0.f, 0.f, 0.f, 0.f);
    float s2 = 0.f;

    const int base = (rc * ROWS_PER_CHUNK + r0) * N_COLS4 + cs * 8 + g;
    #pragma unroll
    for (int i = 0; i < ROWS_PER_THREAD; i++) {
        float4 v = A4[base + i * 32 * N_COLS4];
        c.x += v.x; c.y += v.y; c.z += v.z; c.w += v.w;
        s2 += v.x * v.x + v.y * v.y + v.z * v.z + v.w * v.w;
    }

    // ---- Block reduce: colsums over the 32 row-lanes ----
    __shared__ float4 sh[BLK];
    __shared__ float warp_s2[BLK / 32];
    sh[t] = c;

    #pragma unroll
    for (int off = 16; off > 0; off >>= 1)
        s2 += __shfl_down_sync(0xFFFFFFFFu, s2, off);
    if ((t & 31) == 0) warp_s2[t >> 5] = s2;
    __syncthreads();

    // Tree-reduce sh over the r0 dimension (index = g + 8*r0).
    #pragma unroll
    for (int off = 128; off >= 8; off >>= 1) {
        if (t < off) {
            float4 o = sh[t + off];
            float4 m = sh[t];
            sh[t] = make_float4(m.x + o.x, m.y + o.y, m.z + o.z, m.w + o.w);
        }
        __syncthreads();
    }

    if (t < 8)
        reinterpret_cast<float4*>(g_colpart)[b * 8 + t] = sh[t];
    if (t == 0) {
        float tot = 0.f;
        #pragma unroll
        for (int w = 0; w < BLK / 32; w++) tot += warp_s2[w];
        g_s2part[b] = tot;
    }

    // ---- Last-block-done final reduce ----
    __threadfence();
    __syncthreads();
    __shared__ bool isLast;
    if (t == 0) {
        unsigned int old = atomicAdd(&g_count, 1u);
        isLast = (old == GRID - 1);
    }
    __syncthreads();
    if (!isLast) return;

    // Column sums: thread t handles cols t and t+256.
    // g_colpart layout: [(rc*16+cs)*32 + localcol]; col = cs*32+lc -> float index
    // rc*512 + col. Coalesced across threads.
    double dnrm = 0.0;
    #pragma unroll
    for (int k = 0; k < 2; k++) {
        const int col = t + k * 256;
        float s = 0.f;
        #pragma unroll
        for (int r = 0; r < N_CHUNKS; r++)
            s += g_colpart[r * N_COLS + col];
        dnrm += (double)s * (double)s;
    }
    double ds2 = (t < GRID) ? (double)g_s2part[t] : 0.0;

    // Reduce 256 doubles (8 warps) via shuffles + shared.
    __shared__ double w_nrm[BLK / 32];
    __shared__ double w_s2d[BLK / 32];
    #pragma unroll
    for (int off = 16; off > 0; off >>= 1) {
        dnrm += __shfl_down_sync(0xFFFFFFFFu, dnrm, off);
        ds2  += __shfl_down_sync(0xFFFFFFFFu, ds2, off);
    }
    if ((t & 31) == 0) { w_nrm[t >> 5] = dnrm; w_s2d[t >> 5] = ds2; }
    __syncthreads();

    if (t == 0) {
        double NS = 0.0, S2 = 0.0;
        #pragma unroll
        for (int w = 0; w < BLK / 32; w++) { NS += w_nrm[w]; S2 += w_s2d[w]; }
        const double N = (double)N_ROWS;
        const double C = (double)N_COLS;
        double total = (2.0 * N * S2 - 2.0 * NS) / C;
        out[0] = (float)(total / (N * (N - 1.0)));
        g_count = 0;   // reset for next graph replay
    }
}

extern "C" void kernel_launch(void* const* d_in, const int* in_sizes, int n_in,
                              void* d_out, int out_size) {
    const float* A = (const float*)d_in[0];
    float* out = (float*)d_out;
    (void)in_sizes; (void)n_in; (void)out_size;

    fused_kernel<<<GRID, BLK>>>(A, out);
}